// round 10
// baseline (speedup 1.0000x reference)
#include <cuda_runtime.h>
#include <cuda_bf16.h>
#include <cuda_pipeline.h>
#include <math.h>

#define NROWS 100352   // B*D*H*W tokens == total window rows (1024 windows * 98)
#define CDIM  192
#define SCALE 0.17677669529663687f

typedef __nv_bfloat16 bf16;

// ---------------- scratch (device globals) ----------------------------------
__device__ bf16 g_xw[(size_t)NROWS * CDIM];        // LN'd+rolled+partitioned (window-row major)
__device__ bf16 g_qkv[(size_t)3 * NROWS * CDIM];   // [3][win][head][98][32]
__device__ bf16 g_attnout[(size_t)NROWS * CDIM];   // window-row major, col = head*32+d
__device__ bf16 g_projout[(size_t)NROWS * CDIM];   // token major
__device__ bf16 g_wq[576 * 192];
__device__ bf16 g_wp[192 * 192];
__device__ bf16 g_wf[192 * 192];
__device__ bf16 g_bias6[6 * 9604];                 // rel_bias expanded per head (bf16)
__device__ bf16 g_mb[(size_t)256 * 6 * 98 * 98];   // combined rel_bias + shift mask

// ---------------- helpers ---------------------------------------------------
__device__ __forceinline__ int row_to_token(int row) {
    int win = row / 98;
    int tok = row - win * 98;
    int b = win >> 8, wib = win & 255;
    int wd = wib >> 6, wh = (wib >> 3) & 7, wwi = wib & 7;
    int md = tok / 49; int r2 = tok - md * 49; int mh = r2 / 7; int mw = r2 - mh * 7;
    int d = (wd * 2 + md + 1) & 7;
    int h = wh * 7 + mh + 3; if (h >= 56) h -= 56;
    int w = wwi * 7 + mw + 3; if (w >= 56) w -= 56;
    return ((b * 8 + d) * 56 + h) * 56 + w;
}

__device__ __forceinline__ unsigned smem_u32(const void* p) {
    return (unsigned)__cvta_generic_to_shared(p);
}
__device__ __forceinline__ void ldsm_x4(unsigned r[4], unsigned addr) {
    asm volatile("ldmatrix.sync.aligned.m8n8.x4.shared.b16 {%0,%1,%2,%3}, [%4];"
                 : "=r"(r[0]), "=r"(r[1]), "=r"(r[2]), "=r"(r[3]) : "r"(addr));
}
__device__ __forceinline__ void ldsm_x4_t(unsigned r[4], unsigned addr) {
    asm volatile("ldmatrix.sync.aligned.m8n8.x4.trans.shared.b16 {%0,%1,%2,%3}, [%4];"
                 : "=r"(r[0]), "=r"(r[1]), "=r"(r[2]), "=r"(r[3]) : "r"(addr));
}
__device__ __forceinline__ void mma16816(float c[4], const unsigned a[4], unsigned b0, unsigned b1) {
    asm volatile("mma.sync.aligned.m16n8k16.row.col.f32.bf16.bf16.f32 "
                 "{%0,%1,%2,%3},{%4,%5,%6,%7},{%8,%9},{%0,%1,%2,%3};"
                 : "+f"(c[0]), "+f"(c[1]), "+f"(c[2]), "+f"(c[3])
                 : "r"(a[0]), "r"(a[1]), "r"(a[2]), "r"(a[3]), "r"(b0), "r"(b1));
}
__device__ __forceinline__ unsigned pack2(float lo, float hi) {
    __nv_bfloat162 h = __floats2bfloat162_rn(lo, hi);
    return *reinterpret_cast<unsigned*>(&h);
}

// ---------------- tiny prep kernels -----------------------------------------
__global__ void convert_w_k(const float* __restrict__ qw, const float* __restrict__ pw,
                            const float* __restrict__ fw) {
    int i = blockIdx.x * 256 + threadIdx.x;          // 184320 total
    if (i < 110592)       g_wq[i] = __float2bfloat16(qw[i]);
    else if (i < 147456)  g_wp[i - 110592] = __float2bfloat16(pw[i - 110592]);
    else                  g_wf[i - 147456] = __float2bfloat16(fw[i - 147456]);
}

// expand rel_bias through REL_IDX once: g_bias6[h][q*98+j]
__global__ void bias_expand_k(const float* __restrict__ relb) {
    int i = blockIdx.x * 256 + threadIdx.x;
    if (i >= 9604) return;
    int q = i / 98, j = i - q * 98;
    int nd = q / 49, r2 = q % 49, nh = r2 / 7, nw = r2 % 7;
    int md = j / 49, m2 = j % 49, mh = m2 / 7, mw = m2 % 7;
    int ridx = (nd - md + 1) * 169 + (nh - mh + 6) * 13 + (nw - mw + 6);
    #pragma unroll
    for (int h = 0; h < 6; h++)
        g_bias6[h * 9604 + i] = __float2bfloat16(relb[ridx * 6 + h]);
}

// coalesced combine: g_mb[wh][i] = bias6[h][i] + amask[w][i]
__global__ void mb_combine_k(const float* __restrict__ amask) {
    int i = blockIdx.x * 256 + threadIdx.x;          // i-chunk; gridDim.x = 38
    if (i >= 9604) return;
    int wh = blockIdx.y;                             // 0..1535
    int w = wh / 6, h = wh - w * 6;
    float v = __bfloat162float(g_bias6[h * 9604 + i]) + amask[(size_t)w * 9604 + i];
    g_mb[(size_t)wh * 9604 + i] = __float2bfloat16(v);
}

// ---------------- LayerNorm + roll + window partition ------------------------
__global__ void __launch_bounds__(256) ln_gather_k(const float* __restrict__ x,
        const float* __restrict__ gg, const float* __restrict__ bb) {
    int row = blockIdx.x * 8 + (threadIdx.x >> 5);
    int lane = threadIdx.x & 31;
    int t = row_to_token(row);
    const float* xp = x + (size_t)t * CDIM;
    float v[6]; float s = 0.f;
    #pragma unroll
    for (int j = 0; j < 6; j++) { v[j] = xp[lane + 32 * j]; s += v[j]; }
    #pragma unroll
    for (int o = 16; o > 0; o >>= 1) s += __shfl_xor_sync(0xffffffffu, s, o);
    float mu = s * (1.f / 192.f);
    float var = 0.f;
    #pragma unroll
    for (int j = 0; j < 6; j++) { float dd = v[j] - mu; var += dd * dd; }
    #pragma unroll
    for (int o = 16; o > 0; o >>= 1) var += __shfl_xor_sync(0xffffffffu, var, o);
    float r = rsqrtf(var * (1.f / 192.f) + 1e-5f);
    bf16* op = g_xw + (size_t)row * CDIM;
    #pragma unroll
    for (int j = 0; j < 6; j++) {
        int c = lane + 32 * j;
        op[c] = __float2bfloat16((v[j] - mu) * r * gg[c] + bb[c]);
    }
}

// ---------------- bf16 tensor-core GEMM: C(MxN) = A(Mx192) @ W(Nx192)^T ------
// CTA 128x64, 8 warps (32x32 each). Swizzled smem (stride 192, XOR bank swizzle),
// cp.async two-half K pipeline. MODE 0: QKV scatter. MODE 1: proj token scatter.
// MODE 2: fc1 -> out = shortcut + gelu(acc+bias).
template<int MODE>
__global__ void __launch_bounds__(256) gemm_mma(const float* __restrict__ bias,
        const float* __restrict__ shortcut, float* __restrict__ Out) {
    extern __shared__ __align__(16) char sm[];       // As: 128x384B, Ws at +49152: 64x384B
    const bf16* A = (MODE == 0) ? g_xw : (MODE == 1) ? g_attnout : g_projout;
    const bf16* W = (MODE == 0) ? g_wq : (MODE == 1) ? g_wp : g_wf;
    const int tid = threadIdx.x;
    const int m0 = blockIdx.y * 128, n0 = blockIdx.x * 64;

    // ---- async loads, two K-halves (groups of 8 bf16 = 16B) ----
    #pragma unroll
    for (int half = 0; half < 2; half++) {
        #pragma unroll
        for (int i = 0; i < 6; i++) {
            int u = tid + i * 256;                   // < 1536 = 128 rows * 12 groups
            int row = u / 12, g = u - row * 12 + half * 12;
            __pipeline_memcpy_async(sm + row * 384 + ((g ^ (row & 7)) << 4),
                                    &A[(size_t)(m0 + row) * 192 + g * 8], 16);
        }
        #pragma unroll
        for (int i = 0; i < 3; i++) {
            int u = tid + i * 256;                   // < 768 = 64 rows * 12 groups
            int row = u / 12, g = u - row * 12 + half * 12;
            __pipeline_memcpy_async(sm + 49152 + row * 384 + ((g ^ (row & 7)) << 4),
                                    &W[(size_t)(n0 + row) * 192 + g * 8], 16);
        }
        __pipeline_commit();
    }

    const int warp = tid >> 5, lane = tid & 31;
    const int wm = (warp >> 1) * 32, wn = (warp & 1) * 32;
    const unsigned base_s = smem_u32(sm);
    const unsigned xo = lane & 7;
    const unsigned hA = lane >> 4, hB = (lane >> 3) & 1;
    const unsigned bA0 = base_s + (wm + (lane & 15)) * 384;
    const unsigned bA1 = bA0 + 16 * 384;
    const unsigned bB0 = base_s + 49152 + (wn + ((lane >> 4) & 1) * 8 + (lane & 7)) * 384;
    const unsigned bB1 = bB0 + 16 * 384;

    float acc[2][4][4];
    #pragma unroll
    for (int a = 0; a < 2; a++)
        #pragma unroll
        for (int b = 0; b < 4; b++)
            #pragma unroll
            for (int c = 0; c < 4; c++) acc[a][b][c] = 0.f;

    __pipeline_wait_prior(1);
    __syncthreads();
    #pragma unroll
    for (int ks = 0; ks < 6; ks++) {
        unsigned a0[4], a1[4], b0[4], b1[4];
        unsigned offA = ((2 * ks + hA) ^ xo) << 4, offB = ((2 * ks + hB) ^ xo) << 4;
        ldsm_x4(a0, bA0 + offA); ldsm_x4(a1, bA1 + offA);
        ldsm_x4(b0, bB0 + offB); ldsm_x4(b1, bB1 + offB);
        mma16816(acc[0][0], a0, b0[0], b0[1]); mma16816(acc[0][1], a0, b0[2], b0[3]);
        mma16816(acc[0][2], a0, b1[0], b1[1]); mma16816(acc[0][3], a0, b1[2], b1[3]);
        mma16816(acc[1][0], a1, b0[0], b0[1]); mma16816(acc[1][1], a1, b0[2], b0[3]);
        mma16816(acc[1][2], a1, b1[0], b1[1]); mma16816(acc[1][3], a1, b1[2], b1[3]);
    }
    __pipeline_wait_prior(0);
    __syncthreads();
    #pragma unroll
    for (int ks = 6; ks < 12; ks++) {
        unsigned a0[4], a1[4], b0[4], b1[4];
        unsigned offA = ((2 * ks + hA) ^ xo) << 4, offB = ((2 * ks + hB) ^ xo) << 4;
        ldsm_x4(a0, bA0 + offA); ldsm_x4(a1, bA1 + offA);
        ldsm_x4(b0, bB0 + offB); ldsm_x4(b1, bB1 + offB);
        mma16816(acc[0][0], a0, b0[0], b0[1]); mma16816(acc[0][1], a0, b0[2], b0[3]);
        mma16816(acc[0][2], a0, b1[0], b1[1]); mma16816(acc[0][3], a0, b1[2], b1[3]);
        mma16816(acc[1][0], a1, b0[0], b0[1]); mma16816(acc[1][1], a1, b0[2], b0[3]);
        mma16816(acc[1][2], a1, b1[0], b1[1]); mma16816(acc[1][3], a1, b1[2], b1[3]);
    }

    #pragma unroll
    for (int mt = 0; mt < 2; mt++)
        #pragma unroll
        for (int nt = 0; nt < 4; nt++) {
            int n = n0 + wn + nt * 8 + (lane & 3) * 2;
            int mA = m0 + wm + mt * 16 + (lane >> 2);
            int mB = mA + 8;
            float b0v = bias[n], b1v = bias[n + 1];
            if (MODE == 0) {
                int sI = n / 192, rI = n - sI * 192;
                int hI = rI >> 5, dI = rI & 31;
                {
                    int win = mA / 98, tok = mA - win * 98;
                    bf16* o = g_qkv + (((size_t)sI * 1024 + win) * 6 + hI) * 3136 + tok * 32 + dI;
                    *(__nv_bfloat162*)o = __floats2bfloat162_rn(acc[mt][nt][0] + b0v, acc[mt][nt][1] + b1v);
                }
                {
                    int win = mB / 98, tok = mB - win * 98;
                    bf16* o = g_qkv + (((size_t)sI * 1024 + win) * 6 + hI) * 3136 + tok * 32 + dI;
                    *(__nv_bfloat162*)o = __floats2bfloat162_rn(acc[mt][nt][2] + b0v, acc[mt][nt][3] + b1v);
                }
            } else if (MODE == 1) {
                int tA = row_to_token(mA), tB = row_to_token(mB);
                *(__nv_bfloat162*)&g_projout[(size_t)tA * 192 + n] =
                    __floats2bfloat162_rn(acc[mt][nt][0] + b0v, acc[mt][nt][1] + b1v);
                *(__nv_bfloat162*)&g_projout[(size_t)tB * 192 + n] =
                    __floats2bfloat162_rn(acc[mt][nt][2] + b0v, acc[mt][nt][3] + b1v);
            } else {
                #pragma unroll
                for (int half = 0; half < 2; half++) {
                    int m = half ? mB : mA;
                    float va = acc[mt][nt][half * 2 + 0] + b0v;
                    float vb = acc[mt][nt][half * 2 + 1] + b1v;
                    va = 0.5f * va * (1.f + erff(va * 0.70710678118654752f));
                    vb = 0.5f * vb * (1.f + erff(vb * 0.70710678118654752f));
                    size_t off = (size_t)m * 192 + n;
                    float2 s2 = *(const float2*)&shortcut[off];
                    *(float2*)&Out[off] = make_float2(s2.x + va, s2.y + vb);
                }
            }
        }
}

// ---------------- attention: 7 warps, one q-tile per warp --------------------
__global__ void __launch_bounds__(224) attn_mma() {
    __shared__ __align__(16) bf16 Qs[112 * 40];
    __shared__ __align__(16) bf16 Ks[112 * 40];
    __shared__ __align__(16) bf16 Vs[112 * 40];
    const int win = blockIdx.x / 6, head = blockIdx.x - win * 6;
    const int tid = threadIdx.x, warp = tid >> 5, lane = tid & 31;
    const size_t base = ((size_t)win * 6 + head) * 3136;
    const uint4* qg = (const uint4*)(g_qkv + base);
    const uint4* kg = (const uint4*)(g_qkv + (size_t)NROWS * CDIM + base);
    const uint4* vg = (const uint4*)(g_qkv + (size_t)2 * NROWS * CDIM + base);
    for (int u = tid; u < 392; u += 224) {              // 98 rows * 4 uint4
        int row = u >> 2, c8 = u & 3;
        ((uint4*)Qs)[row * 5 + c8] = qg[u];
        ((uint4*)Ks)[row * 5 + c8] = kg[u];
        ((uint4*)Vs)[row * 5 + c8] = vg[u];
    }
    if (tid < 70) {                                     // zero V pad rows 98..111
        int row = 98 + tid / 5, c = tid - (tid / 5) * 5;
        ((uint4*)Vs)[row * 5 + c] = make_uint4(0, 0, 0, 0);
    }
    __syncthreads();

    const bf16* mbrow = g_mb + ((size_t)(win & 255) * 6 + head) * 9604;
    const unsigned sQ = smem_u32(Qs), sK = smem_u32(Ks), sV = smem_u32(Vs);
    const unsigned qoff = ((lane & 15) * 40 + (lane >> 4) * 8) * 2;
    const unsigned koff = ((((lane >> 4) & 1) * 8 + (lane & 7)) * 40 + ((lane >> 3) & 1) * 8) * 2;
    const unsigned voff = ((((lane >> 3) & 1) * 8 + (lane & 7)) * 40 + ((lane >> 4) & 1) * 8) * 2;

    {
        const int q0 = warp * 16;                       // warp 0..6 -> tiles 0..6
        unsigned a0[4], a1[4];
        ldsm_x4(a0, sQ + q0 * 80 + qoff);
        ldsm_x4(a1, sQ + q0 * 80 + qoff + 32);

        const int rA = q0 + (lane >> 2), rB = rA + 8;
        const bool okA = rA < 98, okB = rB < 98;
        const int j0base = (lane & 3) * 2;
        unsigned pA[14], pB[14];
        float mxA = -1e30f, mxB = -1e30f;

        #pragma unroll
        for (int p = 0; p < 7; p++) {
            float s0[4] = {0.f, 0.f, 0.f, 0.f}, s1[4] = {0.f, 0.f, 0.f, 0.f};
            unsigned b[4];
            ldsm_x4(b, sK + p * 16 * 80 + koff);
            mma16816(s0, a0, b[0], b[1]);
            mma16816(s1, a0, b[2], b[3]);
            ldsm_x4(b, sK + p * 16 * 80 + koff + 32);
            mma16816(s0, a1, b[0], b[1]);
            mma16816(s1, a1, b[2], b[3]);
            #pragma unroll
            for (int h = 0; h < 2; h++) {
                const float* s = h ? s1 : s0;
                int nt = 2 * p + h;
                int j = nt * 8 + j0base;
                float va0 = s[0] * SCALE, va1 = s[1] * SCALE;
                float vb0 = s[2] * SCALE, vb1 = s[3] * SCALE;
                if (j < 98) {
                    if (okA) {
                        __nv_bfloat162 m2 = *(const __nv_bfloat162*)&mbrow[rA * 98 + j];
                        va0 += __low2float(m2); va1 += __high2float(m2);
                    }
                    if (okB) {
                        __nv_bfloat162 m2 = *(const __nv_bfloat162*)&mbrow[rB * 98 + j];
                        vb0 += __low2float(m2); vb1 += __high2float(m2);
                    }
                } else { va0 = va1 = vb0 = vb1 = -1e30f; }
                mxA = fmaxf(mxA, fmaxf(va0, va1));
                mxB = fmaxf(mxB, fmaxf(vb0, vb1));
                pA[nt] = pack2(va0, va1);
                pB[nt] = pack2(vb0, vb1);
            }
        }
        mxA = fmaxf(mxA, __shfl_xor_sync(0xffffffffu, mxA, 1));
        mxA = fmaxf(mxA, __shfl_xor_sync(0xffffffffu, mxA, 2));
        mxB = fmaxf(mxB, __shfl_xor_sync(0xffffffffu, mxB, 1));
        mxB = fmaxf(mxB, __shfl_xor_sync(0xffffffffu, mxB, 2));

        float sA = 0.f, sB = 0.f;
        #pragma unroll
        for (int nt = 0; nt < 14; nt++) {
            __nv_bfloat162 xa = *reinterpret_cast<__nv_bfloat162*>(&pA[nt]);
            __nv_bfloat162 xb = *reinterpret_cast<__nv_bfloat162*>(&pB[nt]);
            float e0 = __expf(__low2float(xa) - mxA), e1 = __expf(__high2float(xa) - mxA);
            float e2 = __expf(__low2float(xb) - mxB), e3 = __expf(__high2float(xb) - mxB);
            sA += e0 + e1; sB += e2 + e3;
            pA[nt] = pack2(e0, e1);
            pB[nt] = pack2(e2, e3);
        }
        sA += __shfl_xor_sync(0xffffffffu, sA, 1);
        sA += __shfl_xor_sync(0xffffffffu, sA, 2);
        sB += __shfl_xor_sync(0xffffffffu, sB, 1);
        sB += __shfl_xor_sync(0xffffffffu, sB, 2);
        const float invA = 1.f / sA, invB = 1.f / sB;

        float oacc[4][4];
        #pragma unroll
        for (int i = 0; i < 4; i++)
            #pragma unroll
            for (int j = 0; j < 4; j++) oacc[i][j] = 0.f;

        #pragma unroll
        for (int kt = 0; kt < 7; kt++) {
            unsigned pa[4];
            pa[0] = pA[2 * kt];     pa[1] = pB[2 * kt];
            pa[2] = pA[2 * kt + 1]; pa[3] = pB[2 * kt + 1];
            #pragma unroll
            for (int dp = 0; dp < 2; dp++) {
                unsigned b[4];
                ldsm_x4_t(b, sV + kt * 16 * 80 + voff + dp * 32);
                mma16816(oacc[2 * dp],     pa, b[0], b[1]);
                mma16816(oacc[2 * dp + 1], pa, b[2], b[3]);
            }
        }

        #pragma unroll
        for (int dt = 0; dt < 4; dt++) {
            int d = head * 32 + dt * 8 + (lane & 3) * 2;
            if (okA)
                *(__nv_bfloat162*)&g_attnout[(size_t)(win * 98 + rA) * 192 + d] =
                    __floats2bfloat162_rn(oacc[dt][0] * invA, oacc[dt][1] * invA);
            if (okB)
                *(__nv_bfloat162*)&g_attnout[(size_t)(win * 98 + rB) * 192 + d] =
                    __floats2bfloat162_rn(oacc[dt][2] * invB, oacc[dt][3] * invB);
        }
    }
}

// ---------------- launch ----------------------------------------------------
extern "C" void kernel_launch(void* const* d_in, const int* in_sizes, int n_in,
                              void* d_out, int out_size) {
    const float* x     = (const float*)d_in[0];
    const float* amask = (const float*)d_in[1];
    const float* n1g   = (const float*)d_in[2];
    const float* n1b   = (const float*)d_in[3];
    const float* qkvw  = (const float*)d_in[4];
    const float* qkvb  = (const float*)d_in[5];
    const float* relb  = (const float*)d_in[6];
    const float* projw = (const float*)d_in[7];
    const float* projb = (const float*)d_in[8];
    const float* fc1w  = (const float*)d_in[9];
    const float* fc1b  = (const float*)d_in[10];
    float* out = (float*)d_out;
    (void)in_sizes; (void)n_in; (void)out_size;

    const int SMEM = (128 + 64) * 192 * 2;   // 73728 B (swizzled, no padding)
    cudaFuncSetAttribute(gemm_mma<0>, cudaFuncAttributeMaxDynamicSharedMemorySize, SMEM);
    cudaFuncSetAttribute(gemm_mma<1>, cudaFuncAttributeMaxDynamicSharedMemorySize, SMEM);
    cudaFuncSetAttribute(gemm_mma<2>, cudaFuncAttributeMaxDynamicSharedMemorySize, SMEM);

    convert_w_k<<<720, 256>>>(qkvw, projw, fc1w);
    bias_expand_k<<<38, 256>>>(relb);
    mb_combine_k<<<dim3(38, 1536), 256>>>(amask);
    ln_gather_k<<<12544, 256>>>(x, n1g, n1b);
    gemm_mma<0><<<dim3(9, 784), 256, SMEM>>>(qkvb, nullptr, nullptr);
    attn_mma<<<6144, 224>>>();
    gemm_mma<1><<<dim3(3, 784), 256, SMEM>>>(projb, nullptr, nullptr);
    gemm_mma<2><<<dim3(3, 784), 256, SMEM>>>(fc1b, x, out);
}

// round 11
// speedup vs baseline: 1.0171x; 1.0171x over previous
#include <cuda_runtime.h>
#include <cuda_bf16.h>
#include <cuda_pipeline.h>
#include <math.h>

#define NROWS 100352   // B*D*H*W tokens == total window rows (1024 windows * 98)
#define CDIM  192
#define SCALE 0.17677669529663687f

typedef __nv_bfloat16 bf16;

// ---------------- scratch (device globals) ----------------------------------
__device__ bf16 g_xw[(size_t)NROWS * CDIM];        // LN'd+rolled+partitioned (window-row major)
__device__ bf16 g_qkv[(size_t)3 * NROWS * CDIM];   // [3][win][head][98][32]
__device__ bf16 g_attnout[(size_t)NROWS * CDIM];   // window-row major, col = head*32+d
__device__ bf16 g_projout[(size_t)NROWS * CDIM];   // token major
__device__ bf16 g_wq[576 * 192];
__device__ bf16 g_wp[192 * 192];
__device__ bf16 g_wf[192 * 192];
__device__ bf16 g_bias6[6 * 9604];                 // rel_bias expanded per head (bf16)
__device__ bf16 g_mb[(size_t)256 * 6 * 98 * 98];   // combined rel_bias + shift mask

// ---------------- helpers ---------------------------------------------------
__device__ __forceinline__ int row_to_token(int row) {
    int win = row / 98;
    int tok = row - win * 98;
    int b = win >> 8, wib = win & 255;
    int wd = wib >> 6, wh = (wib >> 3) & 7, wwi = wib & 7;
    int md = tok / 49; int r2 = tok - md * 49; int mh = r2 / 7; int mw = r2 - mh * 7;
    int d = (wd * 2 + md + 1) & 7;
    int h = wh * 7 + mh + 3; if (h >= 56) h -= 56;
    int w = wwi * 7 + mw + 3; if (w >= 56) w -= 56;
    return ((b * 8 + d) * 56 + h) * 56 + w;
}

__device__ __forceinline__ unsigned smem_u32(const void* p) {
    return (unsigned)__cvta_generic_to_shared(p);
}
__device__ __forceinline__ void ldsm_x4(unsigned r[4], unsigned addr) {
    asm volatile("ldmatrix.sync.aligned.m8n8.x4.shared.b16 {%0,%1,%2,%3}, [%4];"
                 : "=r"(r[0]), "=r"(r[1]), "=r"(r[2]), "=r"(r[3]) : "r"(addr));
}
__device__ __forceinline__ void ldsm_x4_t(unsigned r[4], unsigned addr) {
    asm volatile("ldmatrix.sync.aligned.m8n8.x4.trans.shared.b16 {%0,%1,%2,%3}, [%4];"
                 : "=r"(r[0]), "=r"(r[1]), "=r"(r[2]), "=r"(r[3]) : "r"(addr));
}
__device__ __forceinline__ void mma16816(float c[4], const unsigned a[4], unsigned b0, unsigned b1) {
    asm volatile("mma.sync.aligned.m16n8k16.row.col.f32.bf16.bf16.f32 "
                 "{%0,%1,%2,%3},{%4,%5,%6,%7},{%8,%9},{%0,%1,%2,%3};"
                 : "+f"(c[0]), "+f"(c[1]), "+f"(c[2]), "+f"(c[3])
                 : "r"(a[0]), "r"(a[1]), "r"(a[2]), "r"(a[3]), "r"(b0), "r"(b1));
}
__device__ __forceinline__ unsigned pack2(float lo, float hi) {
    __nv_bfloat162 h = __floats2bfloat162_rn(lo, hi);
    return *reinterpret_cast<unsigned*>(&h);
}

// ---------------- tiny prep kernels -----------------------------------------
__global__ void convert_w_k(const float* __restrict__ qw, const float* __restrict__ pw,
                            const float* __restrict__ fw) {
    int i = blockIdx.x * 256 + threadIdx.x;          // 184320 total
    if (i < 110592)       g_wq[i] = __float2bfloat16(qw[i]);
    else if (i < 147456)  g_wp[i - 110592] = __float2bfloat16(pw[i - 110592]);
    else                  g_wf[i - 147456] = __float2bfloat16(fw[i - 147456]);
}

// expand rel_bias through REL_IDX once: g_bias6[h][q*98+j]
__global__ void bias_expand_k(const float* __restrict__ relb) {
    int i = blockIdx.x * 256 + threadIdx.x;
    if (i >= 9604) return;
    int q = i / 98, j = i - q * 98;
    int nd = q / 49, r2 = q % 49, nh = r2 / 7, nw = r2 % 7;
    int md = j / 49, m2 = j % 49, mh = m2 / 7, mw = m2 % 7;
    int ridx = (nd - md + 1) * 169 + (nh - mh + 6) * 13 + (nw - mw + 6);
    #pragma unroll
    for (int h = 0; h < 6; h++)
        g_bias6[h * 9604 + i] = __float2bfloat16(relb[ridx * 6 + h]);
}

// coalesced combine: g_mb[wh][i] = bias6[h][i] + amask[w][i]
__global__ void mb_combine_k(const float* __restrict__ amask) {
    int i = blockIdx.x * 256 + threadIdx.x;          // i-chunk; gridDim.x = 38
    if (i >= 9604) return;
    int wh = blockIdx.y;                             // 0..1535
    int w = wh / 6, h = wh - w * 6;
    float v = __bfloat162float(g_bias6[h * 9604 + i]) + amask[(size_t)w * 9604 + i];
    g_mb[(size_t)wh * 9604 + i] = __float2bfloat16(v);
}

// ---------------- LayerNorm + roll + window partition ------------------------
__global__ void __launch_bounds__(256) ln_gather_k(const float* __restrict__ x,
        const float* __restrict__ gg, const float* __restrict__ bb) {
    int row = blockIdx.x * 8 + (threadIdx.x >> 5);
    int lane = threadIdx.x & 31;
    int t = row_to_token(row);
    const float* xp = x + (size_t)t * CDIM;
    float v[6]; float s = 0.f;
    #pragma unroll
    for (int j = 0; j < 6; j++) { v[j] = xp[lane + 32 * j]; s += v[j]; }
    #pragma unroll
    for (int o = 16; o > 0; o >>= 1) s += __shfl_xor_sync(0xffffffffu, s, o);
    float mu = s * (1.f / 192.f);
    float var = 0.f;
    #pragma unroll
    for (int j = 0; j < 6; j++) { float dd = v[j] - mu; var += dd * dd; }
    #pragma unroll
    for (int o = 16; o > 0; o >>= 1) var += __shfl_xor_sync(0xffffffffu, var, o);
    float r = rsqrtf(var * (1.f / 192.f) + 1e-5f);
    bf16* op = g_xw + (size_t)row * CDIM;
    #pragma unroll
    for (int j = 0; j < 6; j++) {
        int c = lane + 32 * j;
        op[c] = __float2bfloat16((v[j] - mu) * r * gg[c] + bb[c]);
    }
}

// ---------------- bf16 tensor-core GEMM: C(MxN) = A(Mx192) @ W(Nx192)^T ------
// CTA 128x64, 8 warps (32x32 each). Swizzled smem (stride 192, XOR bank swizzle),
// cp.async two-half K pipeline. MODE 0: QKV scatter. MODE 1: proj token scatter.
// MODE 2: fc1 -> out = shortcut + gelu(acc+bias).
template<int MODE>
__global__ void __launch_bounds__(256) gemm_mma(const float* __restrict__ bias,
        const float* __restrict__ shortcut, float* __restrict__ Out) {
    extern __shared__ __align__(16) char sm[];       // As: 128x384B, Ws at +49152: 64x384B
    const bf16* A = (MODE == 0) ? g_xw : (MODE == 1) ? g_attnout : g_projout;
    const bf16* W = (MODE == 0) ? g_wq : (MODE == 1) ? g_wp : g_wf;
    const int tid = threadIdx.x;
    const int m0 = blockIdx.y * 128, n0 = blockIdx.x * 64;

    // ---- async loads, two K-halves (groups of 8 bf16 = 16B) ----
    #pragma unroll
    for (int half = 0; half < 2; half++) {
        #pragma unroll
        for (int i = 0; i < 6; i++) {
            int u = tid + i * 256;                   // < 1536 = 128 rows * 12 groups
            int row = u / 12, g = u - row * 12 + half * 12;
            __pipeline_memcpy_async(sm + row * 384 + ((g ^ (row & 7)) << 4),
                                    &A[(size_t)(m0 + row) * 192 + g * 8], 16);
        }
        #pragma unroll
        for (int i = 0; i < 3; i++) {
            int u = tid + i * 256;                   // < 768 = 64 rows * 12 groups
            int row = u / 12, g = u - row * 12 + half * 12;
            __pipeline_memcpy_async(sm + 49152 + row * 384 + ((g ^ (row & 7)) << 4),
                                    &W[(size_t)(n0 + row) * 192 + g * 8], 16);
        }
        __pipeline_commit();
    }

    const int warp = tid >> 5, lane = tid & 31;
    const int wm = (warp >> 1) * 32, wn = (warp & 1) * 32;
    const unsigned base_s = smem_u32(sm);
    const unsigned xo = lane & 7;
    const unsigned hA = lane >> 4, hB = (lane >> 3) & 1;
    const unsigned bA0 = base_s + (wm + (lane & 15)) * 384;
    const unsigned bA1 = bA0 + 16 * 384;
    const unsigned bB0 = base_s + 49152 + (wn + ((lane >> 4) & 1) * 8 + (lane & 7)) * 384;
    const unsigned bB1 = bB0 + 16 * 384;

    float acc[2][4][4];
    #pragma unroll
    for (int a = 0; a < 2; a++)
        #pragma unroll
        for (int b = 0; b < 4; b++)
            #pragma unroll
            for (int c = 0; c < 4; c++) acc[a][b][c] = 0.f;

    __pipeline_wait_prior(1);
    __syncthreads();
    #pragma unroll
    for (int ks = 0; ks < 6; ks++) {
        unsigned a0[4], a1[4], b0[4], b1[4];
        unsigned offA = ((2 * ks + hA) ^ xo) << 4, offB = ((2 * ks + hB) ^ xo) << 4;
        ldsm_x4(a0, bA0 + offA); ldsm_x4(a1, bA1 + offA);
        ldsm_x4(b0, bB0 + offB); ldsm_x4(b1, bB1 + offB);
        mma16816(acc[0][0], a0, b0[0], b0[1]); mma16816(acc[0][1], a0, b0[2], b0[3]);
        mma16816(acc[0][2], a0, b1[0], b1[1]); mma16816(acc[0][3], a0, b1[2], b1[3]);
        mma16816(acc[1][0], a1, b0[0], b0[1]); mma16816(acc[1][1], a1, b0[2], b0[3]);
        mma16816(acc[1][2], a1, b1[0], b1[1]); mma16816(acc[1][3], a1, b1[2], b1[3]);
    }
    __pipeline_wait_prior(0);
    __syncthreads();
    #pragma unroll
    for (int ks = 6; ks < 12; ks++) {
        unsigned a0[4], a1[4], b0[4], b1[4];
        unsigned offA = ((2 * ks + hA) ^ xo) << 4, offB = ((2 * ks + hB) ^ xo) << 4;
        ldsm_x4(a0, bA0 + offA); ldsm_x4(a1, bA1 + offA);
        ldsm_x4(b0, bB0 + offB); ldsm_x4(b1, bB1 + offB);
        mma16816(acc[0][0], a0, b0[0], b0[1]); mma16816(acc[0][1], a0, b0[2], b0[3]);
        mma16816(acc[0][2], a0, b1[0], b1[1]); mma16816(acc[0][3], a0, b1[2], b1[3]);
        mma16816(acc[1][0], a1, b0[0], b0[1]); mma16816(acc[1][1], a1, b0[2], b0[3]);
        mma16816(acc[1][2], a1, b1[0], b1[1]); mma16816(acc[1][3], a1, b1[2], b1[3]);
    }

    #pragma unroll
    for (int mt = 0; mt < 2; mt++)
        #pragma unroll
        for (int nt = 0; nt < 4; nt++) {
            int n = n0 + wn + nt * 8 + (lane & 3) * 2;
            int mA = m0 + wm + mt * 16 + (lane >> 2);
            int mB = mA + 8;
            float b0v = bias[n], b1v = bias[n + 1];
            if (MODE == 0) {
                int sI = n / 192, rI = n - sI * 192;
                int hI = rI >> 5, dI = rI & 31;
                {
                    int win = mA / 98, tok = mA - win * 98;
                    bf16* o = g_qkv + (((size_t)sI * 1024 + win) * 6 + hI) * 3136 + tok * 32 + dI;
                    *(__nv_bfloat162*)o = __floats2bfloat162_rn(acc[mt][nt][0] + b0v, acc[mt][nt][1] + b1v);
                }
                {
                    int win = mB / 98, tok = mB - win * 98;
                    bf16* o = g_qkv + (((size_t)sI * 1024 + win) * 6 + hI) * 3136 + tok * 32 + dI;
                    *(__nv_bfloat162*)o = __floats2bfloat162_rn(acc[mt][nt][2] + b0v, acc[mt][nt][3] + b1v);
                }
            } else if (MODE == 1) {
                int tA = row_to_token(mA), tB = row_to_token(mB);
                *(__nv_bfloat162*)&g_projout[(size_t)tA * 192 + n] =
                    __floats2bfloat162_rn(acc[mt][nt][0] + b0v, acc[mt][nt][1] + b1v);
                *(__nv_bfloat162*)&g_projout[(size_t)tB * 192 + n] =
                    __floats2bfloat162_rn(acc[mt][nt][2] + b0v, acc[mt][nt][3] + b1v);
            } else {
                #pragma unroll
                for (int half = 0; half < 2; half++) {
                    int m = half ? mB : mA;
                    float va = acc[mt][nt][half * 2 + 0] + b0v;
                    float vb = acc[mt][nt][half * 2 + 1] + b1v;
                    va = 0.5f * va * (1.f + erff(va * 0.70710678118654752f));
                    vb = 0.5f * vb * (1.f + erff(vb * 0.70710678118654752f));
                    size_t off = (size_t)m * 192 + n;
                    float2 s2 = *(const float2*)&shortcut[off];
                    *(float2*)&Out[off] = make_float2(s2.x + va, s2.y + vb);
                }
            }
        }
}

// ---------------- attention: bf16-packed scores, one block per (win, head) --
__global__ void __launch_bounds__(128) attn_mma() {
    __shared__ __align__(16) bf16 Qs[112 * 40];
    __shared__ __align__(16) bf16 Ks[112 * 40];
    __shared__ __align__(16) bf16 Vs[112 * 40];
    const int win = blockIdx.x / 6, head = blockIdx.x - win * 6;
    const int tid = threadIdx.x, warp = tid >> 5, lane = tid & 31;
    const size_t base = ((size_t)win * 6 + head) * 3136;
    const uint4* qg = (const uint4*)(g_qkv + base);
    const uint4* kg = (const uint4*)(g_qkv + (size_t)NROWS * CDIM + base);
    const uint4* vg = (const uint4*)(g_qkv + (size_t)2 * NROWS * CDIM + base);
    for (int u = tid; u < 392; u += 128) {              // 98 rows * 4 uint4
        int row = u >> 2, c8 = u & 3;
        ((uint4*)Qs)[row * 5 + c8] = qg[u];
        ((uint4*)Ks)[row * 5 + c8] = kg[u];
        ((uint4*)Vs)[row * 5 + c8] = vg[u];
    }
    if (tid < 70) {                                     // zero V pad rows 98..111
        int row = 98 + tid / 5, c = tid - (tid / 5) * 5;
        ((uint4*)Vs)[row * 5 + c] = make_uint4(0, 0, 0, 0);
    }
    __syncthreads();

    const bf16* mbrow = g_mb + ((size_t)(win & 255) * 6 + head) * 9604;
    const unsigned sQ = smem_u32(Qs), sK = smem_u32(Ks), sV = smem_u32(Vs);
    const unsigned qoff = ((lane & 15) * 40 + (lane >> 4) * 8) * 2;
    const unsigned koff = ((((lane >> 4) & 1) * 8 + (lane & 7)) * 40 + ((lane >> 3) & 1) * 8) * 2;
    const unsigned voff = ((((lane >> 3) & 1) * 8 + (lane & 7)) * 40 + ((lane >> 4) & 1) * 8) * 2;

    for (int t = warp; t < 7; t += 4) {
        const int q0 = t * 16;
        unsigned a0[4], a1[4];
        ldsm_x4(a0, sQ + q0 * 80 + qoff);
        ldsm_x4(a1, sQ + q0 * 80 + qoff + 32);

        const int rA = q0 + (lane >> 2), rB = rA + 8;
        const bool okA = rA < 98, okB = rB < 98;
        const int j0base = (lane & 3) * 2;
        unsigned pA[14], pB[14];
        float mxA = -1e30f, mxB = -1e30f;

        #pragma unroll
        for (int p = 0; p < 7; p++) {
            float s0[4] = {0.f, 0.f, 0.f, 0.f}, s1[4] = {0.f, 0.f, 0.f, 0.f};
            unsigned b[4];
            ldsm_x4(b, sK + p * 16 * 80 + koff);
            mma16816(s0, a0, b[0], b[1]);
            mma16816(s1, a0, b[2], b[3]);
            ldsm_x4(b, sK + p * 16 * 80 + koff + 32);
            mma16816(s0, a1, b[0], b[1]);
            mma16816(s1, a1, b[2], b[3]);
            #pragma unroll
            for (int h = 0; h < 2; h++) {
                const float* s = h ? s1 : s0;
                int nt = 2 * p + h;
                int j = nt * 8 + j0base;
                float va0 = s[0] * SCALE, va1 = s[1] * SCALE;
                float vb0 = s[2] * SCALE, vb1 = s[3] * SCALE;
                if (j < 98) {
                    if (okA) {
                        __nv_bfloat162 m2 = *(const __nv_bfloat162*)&mbrow[rA * 98 + j];
                        va0 += __low2float(m2); va1 += __high2float(m2);
                    }
                    if (okB) {
                        __nv_bfloat162 m2 = *(const __nv_bfloat162*)&mbrow[rB * 98 + j];
                        vb0 += __low2float(m2); vb1 += __high2float(m2);
                    }
                } else { va0 = va1 = vb0 = vb1 = -1e30f; }
                mxA = fmaxf(mxA, fmaxf(va0, va1));
                mxB = fmaxf(mxB, fmaxf(vb0, vb1));
                pA[nt] = pack2(va0, va1);
                pB[nt] = pack2(vb0, vb1);
            }
        }
        mxA = fmaxf(mxA, __shfl_xor_sync(0xffffffffu, mxA, 1));
        mxA = fmaxf(mxA, __shfl_xor_sync(0xffffffffu, mxA, 2));
        mxB = fmaxf(mxB, __shfl_xor_sync(0xffffffffu, mxB, 1));
        mxB = fmaxf(mxB, __shfl_xor_sync(0xffffffffu, mxB, 2));

        float sA = 0.f, sB = 0.f;
        #pragma unroll
        for (int nt = 0; nt < 14; nt++) {
            __nv_bfloat162 xa = *reinterpret_cast<__nv_bfloat162*>(&pA[nt]);
            __nv_bfloat162 xb = *reinterpret_cast<__nv_bfloat162*>(&pB[nt]);
            float e0 = __expf(__low2float(xa) - mxA), e1 = __expf(__high2float(xa) - mxA);
            float e2 = __expf(__low2float(xb) - mxB), e3 = __expf(__high2float(xb) - mxB);
            sA += e0 + e1; sB += e2 + e3;
            pA[nt] = pack2(e0, e1);
            pB[nt] = pack2(e2, e3);
        }
        sA += __shfl_xor_sync(0xffffffffu, sA, 1);
        sA += __shfl_xor_sync(0xffffffffu, sA, 2);
        sB += __shfl_xor_sync(0xffffffffu, sB, 1);
        sB += __shfl_xor_sync(0xffffffffu, sB, 2);
        const float invA = 1.f / sA, invB = 1.f / sB;

        float oacc[4][4];
        #pragma unroll
        for (int i = 0; i < 4; i++)
            #pragma unroll
            for (int j = 0; j < 4; j++) oacc[i][j] = 0.f;

        #pragma unroll
        for (int kt = 0; kt < 7; kt++) {
            unsigned pa[4];
            pa[0] = pA[2 * kt];     pa[1] = pB[2 * kt];
            pa[2] = pA[2 * kt + 1]; pa[3] = pB[2 * kt + 1];
            #pragma unroll
            for (int dp = 0; dp < 2; dp++) {
                unsigned b[4];
                ldsm_x4_t(b, sV + kt * 16 * 80 + voff + dp * 32);
                mma16816(oacc[2 * dp],     pa, b[0], b[1]);
                mma16816(oacc[2 * dp + 1], pa, b[2], b[3]);
            }
        }

        #pragma unroll
        for (int dt = 0; dt < 4; dt++) {
            int d = head * 32 + dt * 8 + (lane & 3) * 2;
            if (okA)
                *(__nv_bfloat162*)&g_attnout[(size_t)(win * 98 + rA) * 192 + d] =
                    __floats2bfloat162_rn(oacc[dt][0] * invA, oacc[dt][1] * invA);
            if (okB)
                *(__nv_bfloat162*)&g_attnout[(size_t)(win * 98 + rB) * 192 + d] =
                    __floats2bfloat162_rn(oacc[dt][2] * invB, oacc[dt][3] * invB);
        }
    }
}

// ---------------- launch ----------------------------------------------------
extern "C" void kernel_launch(void* const* d_in, const int* in_sizes, int n_in,
                              void* d_out, int out_size) {
    const float* x     = (const float*)d_in[0];
    const float* amask = (const float*)d_in[1];
    const float* n1g   = (const float*)d_in[2];
    const float* n1b   = (const float*)d_in[3];
    const float* qkvw  = (const float*)d_in[4];
    const float* qkvb  = (const float*)d_in[5];
    const float* relb  = (const float*)d_in[6];
    const float* projw = (const float*)d_in[7];
    const float* projb = (const float*)d_in[8];
    const float* fc1w  = (const float*)d_in[9];
    const float* fc1b  = (const float*)d_in[10];
    float* out = (float*)d_out;
    (void)in_sizes; (void)n_in; (void)out_size;

    const int SMEM = (128 + 64) * 192 * 2;   // 73728 B (swizzled, no padding)
    cudaFuncSetAttribute(gemm_mma<0>, cudaFuncAttributeMaxDynamicSharedMemorySize, SMEM);
    cudaFuncSetAttribute(gemm_mma<1>, cudaFuncAttributeMaxDynamicSharedMemorySize, SMEM);
    cudaFuncSetAttribute(gemm_mma<2>, cudaFuncAttributeMaxDynamicSharedMemorySize, SMEM);

    convert_w_k<<<720, 256>>>(qkvw, projw, fc1w);
    bias_expand_k<<<38, 256>>>(relb);
    mb_combine_k<<<dim3(38, 1536), 256>>>(amask);
    ln_gather_k<<<12544, 256>>>(x, n1g, n1b);
    gemm_mma<0><<<dim3(9, 784), 256, SMEM>>>(qkvb, nullptr, nullptr);
    attn_mma<<<6144, 128>>>();
    gemm_mma<1><<<dim3(3, 784), 256, SMEM>>>(projb, nullptr, nullptr);
    gemm_mma<2><<<dim3(3, 784), 256, SMEM>>>(fc1b, x, out);
}

// round 12
// speedup vs baseline: 1.2039x; 1.1837x over previous
#include <cuda_runtime.h>
#include <cuda_bf16.h>
#include <cuda_pipeline.h>
#include <math.h>

#define NROWS 100352   // B*D*H*W tokens == total window rows (1024 windows * 98)
#define CDIM  192
#define SCALE 0.17677669529663687f
#define MBSTRIDE 9616  // 9604 padded to 16B-aligned row (bf16)

typedef __nv_bfloat16 bf16;

// ---------------- scratch (device globals) ----------------------------------
__device__ bf16 g_xw[(size_t)NROWS * CDIM];        // LN'd+rolled+partitioned (window-row major)
__device__ bf16 g_qkv[(size_t)3 * NROWS * CDIM];   // [3][win][head][98][32]
__device__ bf16 g_attnout[(size_t)NROWS * CDIM];   // window-row major, col = head*32+d
__device__ bf16 g_projout[(size_t)NROWS * CDIM];   // token major
__device__ bf16 g_wq[576 * 192];
__device__ bf16 g_wp[192 * 192];
__device__ bf16 g_wf[192 * 192];
__device__ bf16 g_mb[(size_t)256 * 6 * MBSTRIDE];  // combined rel_bias + shift mask (padded rows)

// ---------------- helpers ---------------------------------------------------
__device__ __forceinline__ int row_to_token(int row) {
    int win = row / 98;
    int tok = row - win * 98;
    int b = win >> 8, wib = win & 255;
    int wd = wib >> 6, wh = (wib >> 3) & 7, wwi = wib & 7;
    int md = tok / 49; int r2 = tok - md * 49; int mh = r2 / 7; int mw = r2 - mh * 7;
    int d = (wd * 2 + md + 1) & 7;
    int h = wh * 7 + mh + 3; if (h >= 56) h -= 56;
    int w = wwi * 7 + mw + 3; if (w >= 56) w -= 56;
    return ((b * 8 + d) * 56 + h) * 56 + w;
}

__device__ __forceinline__ unsigned smem_u32(const void* p) {
    return (unsigned)__cvta_generic_to_shared(p);
}
__device__ __forceinline__ void ldsm_x4(unsigned r[4], unsigned addr) {
    asm volatile("ldmatrix.sync.aligned.m8n8.x4.shared.b16 {%0,%1,%2,%3}, [%4];"
                 : "=r"(r[0]), "=r"(r[1]), "=r"(r[2]), "=r"(r[3]) : "r"(addr));
}
__device__ __forceinline__ void ldsm_x4_t(unsigned r[4], unsigned addr) {
    asm volatile("ldmatrix.sync.aligned.m8n8.x4.trans.shared.b16 {%0,%1,%2,%3}, [%4];"
                 : "=r"(r[0]), "=r"(r[1]), "=r"(r[2]), "=r"(r[3]) : "r"(addr));
}
__device__ __forceinline__ void mma16816(float c[4], const unsigned a[4], unsigned b0, unsigned b1) {
    asm volatile("mma.sync.aligned.m16n8k16.row.col.f32.bf16.bf16.f32 "
                 "{%0,%1,%2,%3},{%4,%5,%6,%7},{%8,%9},{%0,%1,%2,%3};"
                 : "+f"(c[0]), "+f"(c[1]), "+f"(c[2]), "+f"(c[3])
                 : "r"(a[0]), "r"(a[1]), "r"(a[2]), "r"(a[3]), "r"(b0), "r"(b1));
}
__device__ __forceinline__ unsigned pack2(float lo, float hi) {
    __nv_bfloat162 h = __floats2bfloat162_rn(lo, hi);
    return *reinterpret_cast<unsigned*>(&h);
}

// ---------------- tiny prep kernels -----------------------------------------
__global__ void convert_w_k(const float* __restrict__ qw, const float* __restrict__ pw,
                            const float* __restrict__ fw) {
    int i = blockIdx.x * 256 + threadIdx.x;          // 184320 total
    if (i < 110592)       g_wq[i] = __float2bfloat16(qw[i]);
    else if (i < 147456)  g_wp[i - 110592] = __float2bfloat16(pw[i - 110592]);
    else                  g_wf[i - 147456] = __float2bfloat16(fw[i - 147456]);
}

// combined mask+bias table (R9 form, padded stride):
// g_mb[(w*6+h)*MBSTRIDE + i] = rel_bias[REL_IDX[q][j]][h] + amask[w][q][j]
__global__ void mb_combine_k(const float* __restrict__ amask, const float* __restrict__ relb) {
    int idx = blockIdx.x * 256 + threadIdx.x;        // 256*9604 total
    if (idx >= 256 * 9604) return;
    int w = idx / 9604, i = idx - w * 9604;
    int q = i / 98, j = i - q * 98;
    int nd = q / 49, r2 = q % 49, nh = r2 / 7, nw = r2 % 7;
    int md = j / 49, m2 = j % 49, mh = m2 / 7, mw = m2 % 7;
    int ridx = (nd - md + 1) * 169 + (nh - mh + 6) * 13 + (nw - mw + 6);
    float m = amask[(size_t)w * 9604 + i];
    #pragma unroll
    for (int h = 0; h < 6; h++)
        g_mb[((size_t)w * 6 + h) * MBSTRIDE + i] = __float2bfloat16(relb[ridx * 6 + h] + m);
}

// ---------------- LayerNorm + roll + window partition ------------------------
__global__ void __launch_bounds__(256) ln_gather_k(const float* __restrict__ x,
        const float* __restrict__ gg, const float* __restrict__ bb) {
    int row = blockIdx.x * 8 + (threadIdx.x >> 5);
    int lane = threadIdx.x & 31;
    int t = row_to_token(row);
    const float* xp = x + (size_t)t * CDIM;
    float v[6]; float s = 0.f;
    #pragma unroll
    for (int j = 0; j < 6; j++) { v[j] = xp[lane + 32 * j]; s += v[j]; }
    #pragma unroll
    for (int o = 16; o > 0; o >>= 1) s += __shfl_xor_sync(0xffffffffu, s, o);
    float mu = s * (1.f / 192.f);
    float var = 0.f;
    #pragma unroll
    for (int j = 0; j < 6; j++) { float dd = v[j] - mu; var += dd * dd; }
    #pragma unroll
    for (int o = 16; o > 0; o >>= 1) var += __shfl_xor_sync(0xffffffffu, var, o);
    float r = rsqrtf(var * (1.f / 192.f) + 1e-5f);
    bf16* op = g_xw + (size_t)row * CDIM;
    #pragma unroll
    for (int j = 0; j < 6; j++) {
        int c = lane + 32 * j;
        op[c] = __float2bfloat16((v[j] - mu) * r * gg[c] + bb[c]);
    }
}

// ---------------- bf16 tensor-core GEMM: C(MxN) = A(Mx192) @ W(Nx192)^T ------
// CTA 128x64, 8 warps (32x32 each). Swizzled smem (stride 192, XOR bank swizzle),
// cp.async two-half K pipeline. MODE 0: QKV scatter. MODE 1: proj token scatter.
// MODE 2: fc1 -> out = shortcut + gelu(acc+bias).
template<int MODE>
__global__ void __launch_bounds__(256) gemm_mma(const float* __restrict__ bias,
        const float* __restrict__ shortcut, float* __restrict__ Out) {
    extern __shared__ __align__(16) char sm[];       // As: 128x384B, Ws at +49152: 64x384B
    const bf16* A = (MODE == 0) ? g_xw : (MODE == 1) ? g_attnout : g_projout;
    const bf16* W = (MODE == 0) ? g_wq : (MODE == 1) ? g_wp : g_wf;
    const int tid = threadIdx.x;
    const int m0 = blockIdx.y * 128, n0 = blockIdx.x * 64;

    // ---- async loads, two K-halves (groups of 8 bf16 = 16B) ----
    #pragma unroll
    for (int half = 0; half < 2; half++) {
        #pragma unroll
        for (int i = 0; i < 6; i++) {
            int u = tid + i * 256;                   // < 1536 = 128 rows * 12 groups
            int row = u / 12, g = u - row * 12 + half * 12;
            __pipeline_memcpy_async(sm + row * 384 + ((g ^ (row & 7)) << 4),
                                    &A[(size_t)(m0 + row) * 192 + g * 8], 16);
        }
        #pragma unroll
        for (int i = 0; i < 3; i++) {
            int u = tid + i * 256;                   // < 768 = 64 rows * 12 groups
            int row = u / 12, g = u - row * 12 + half * 12;
            __pipeline_memcpy_async(sm + 49152 + row * 384 + ((g ^ (row & 7)) << 4),
                                    &W[(size_t)(n0 + row) * 192 + g * 8], 16);
        }
        __pipeline_commit();
    }

    const int warp = tid >> 5, lane = tid & 31;
    const int wm = (warp >> 1) * 32, wn = (warp & 1) * 32;
    const unsigned base_s = smem_u32(sm);
    const unsigned xo = lane & 7;
    const unsigned hA = lane >> 4, hB = (lane >> 3) & 1;
    const unsigned bA0 = base_s + (wm + (lane & 15)) * 384;
    const unsigned bA1 = bA0 + 16 * 384;
    const unsigned bB0 = base_s + 49152 + (wn + ((lane >> 4) & 1) * 8 + (lane & 7)) * 384;
    const unsigned bB1 = bB0 + 16 * 384;

    float acc[2][4][4];
    #pragma unroll
    for (int a = 0; a < 2; a++)
        #pragma unroll
        for (int b = 0; b < 4; b++)
            #pragma unroll
            for (int c = 0; c < 4; c++) acc[a][b][c] = 0.f;

    __pipeline_wait_prior(1);
    __syncthreads();
    #pragma unroll
    for (int ks = 0; ks < 6; ks++) {
        unsigned a0[4], a1[4], b0[4], b1[4];
        unsigned offA = ((2 * ks + hA) ^ xo) << 4, offB = ((2 * ks + hB) ^ xo) << 4;
        ldsm_x4(a0, bA0 + offA); ldsm_x4(a1, bA1 + offA);
        ldsm_x4(b0, bB0 + offB); ldsm_x4(b1, bB1 + offB);
        mma16816(acc[0][0], a0, b0[0], b0[1]); mma16816(acc[0][1], a0, b0[2], b0[3]);
        mma16816(acc[0][2], a0, b1[0], b1[1]); mma16816(acc[0][3], a0, b1[2], b1[3]);
        mma16816(acc[1][0], a1, b0[0], b0[1]); mma16816(acc[1][1], a1, b0[2], b0[3]);
        mma16816(acc[1][2], a1, b1[0], b1[1]); mma16816(acc[1][3], a1, b1[2], b1[3]);
    }
    __pipeline_wait_prior(0);
    __syncthreads();
    #pragma unroll
    for (int ks = 6; ks < 12; ks++) {
        unsigned a0[4], a1[4], b0[4], b1[4];
        unsigned offA = ((2 * ks + hA) ^ xo) << 4, offB = ((2 * ks + hB) ^ xo) << 4;
        ldsm_x4(a0, bA0 + offA); ldsm_x4(a1, bA1 + offA);
        ldsm_x4(b0, bB0 + offB); ldsm_x4(b1, bB1 + offB);
        mma16816(acc[0][0], a0, b0[0], b0[1]); mma16816(acc[0][1], a0, b0[2], b0[3]);
        mma16816(acc[0][2], a0, b1[0], b1[1]); mma16816(acc[0][3], a0, b1[2], b1[3]);
        mma16816(acc[1][0], a1, b0[0], b0[1]); mma16816(acc[1][1], a1, b0[2], b0[3]);
        mma16816(acc[1][2], a1, b1[0], b1[1]); mma16816(acc[1][3], a1, b1[2], b1[3]);
    }

    #pragma unroll
    for (int mt = 0; mt < 2; mt++)
        #pragma unroll
        for (int nt = 0; nt < 4; nt++) {
            int n = n0 + wn + nt * 8 + (lane & 3) * 2;
            int mA = m0 + wm + mt * 16 + (lane >> 2);
            int mB = mA + 8;
            float b0v = bias[n], b1v = bias[n + 1];
            if (MODE == 0) {
                int sI = n / 192, rI = n - sI * 192;
                int hI = rI >> 5, dI = rI & 31;
                {
                    int win = mA / 98, tok = mA - win * 98;
                    bf16* o = g_qkv + (((size_t)sI * 1024 + win) * 6 + hI) * 3136 + tok * 32 + dI;
                    *(__nv_bfloat162*)o = __floats2bfloat162_rn(acc[mt][nt][0] + b0v, acc[mt][nt][1] + b1v);
                }
                {
                    int win = mB / 98, tok = mB - win * 98;
                    bf16* o = g_qkv + (((size_t)sI * 1024 + win) * 6 + hI) * 3136 + tok * 32 + dI;
                    *(__nv_bfloat162*)o = __floats2bfloat162_rn(acc[mt][nt][2] + b0v, acc[mt][nt][3] + b1v);
                }
            } else if (MODE == 1) {
                int tA = row_to_token(mA), tB = row_to_token(mB);
                *(__nv_bfloat162*)&g_projout[(size_t)tA * 192 + n] =
                    __floats2bfloat162_rn(acc[mt][nt][0] + b0v, acc[mt][nt][1] + b1v);
                *(__nv_bfloat162*)&g_projout[(size_t)tB * 192 + n] =
                    __floats2bfloat162_rn(acc[mt][nt][2] + b0v, acc[mt][nt][3] + b1v);
            } else {
                #pragma unroll
                for (int half = 0; half < 2; half++) {
                    int m = half ? mB : mA;
                    float va = acc[mt][nt][half * 2 + 0] + b0v;
                    float vb = acc[mt][nt][half * 2 + 1] + b1v;
                    va = 0.5f * va * (1.f + erff(va * 0.70710678118654752f));
                    vb = 0.5f * vb * (1.f + erff(vb * 0.70710678118654752f));
                    size_t off = (size_t)m * 192 + n;
                    float2 s2 = *(const float2*)&shortcut[off];
                    *(float2*)&Out[off] = make_float2(s2.x + va, s2.y + vb);
                }
            }
        }
}

// ---------------- attention: cp.async staged QKV + mb row in smem ------------
__global__ void __launch_bounds__(128) attn_mma() {
    __shared__ __align__(16) bf16 Qs[112 * 40];
    __shared__ __align__(16) bf16 Ks[112 * 40];
    __shared__ __align__(16) bf16 Vs[112 * 40];
    __shared__ __align__(16) bf16 Ms[MBSTRIDE];       // combined mask+bias row
    const int win = blockIdx.x / 6, head = blockIdx.x - win * 6;
    const int tid = threadIdx.x, warp = tid >> 5, lane = tid & 31;
    const size_t base = ((size_t)win * 6 + head) * 3136;
    const uint4* qg = (const uint4*)(g_qkv + base);
    const uint4* kg = (const uint4*)(g_qkv + (size_t)NROWS * CDIM + base);
    const uint4* vg = (const uint4*)(g_qkv + (size_t)2 * NROWS * CDIM + base);
    const uint4* mg = (const uint4*)(g_mb + ((size_t)(win & 255) * 6 + head) * MBSTRIDE);

    for (int u = tid; u < 392; u += 128) {            // 98 rows * 4 uint4
        int row = u >> 2, c8 = u & 3;
        __pipeline_memcpy_async(&((uint4*)Qs)[row * 5 + c8], &qg[u], 16);
        __pipeline_memcpy_async(&((uint4*)Ks)[row * 5 + c8], &kg[u], 16);
        __pipeline_memcpy_async(&((uint4*)Vs)[row * 5 + c8], &vg[u], 16);
    }
    for (int u = tid; u < MBSTRIDE / 8; u += 128)     // 1202 16B chunks
        __pipeline_memcpy_async(&((uint4*)Ms)[u], &mg[u], 16);
    if (tid < 70) {                                   // zero V pad rows 98..111
        int row = 98 + tid / 5, c = tid - (tid / 5) * 5;
        ((uint4*)Vs)[row * 5 + c] = make_uint4(0, 0, 0, 0);
    }
    __pipeline_commit();
    __pipeline_wait_prior(0);
    __syncthreads();

    const unsigned sQ = smem_u32(Qs), sK = smem_u32(Ks), sV = smem_u32(Vs);
    const unsigned qoff = ((lane & 15) * 40 + (lane >> 4) * 8) * 2;
    const unsigned koff = ((((lane >> 4) & 1) * 8 + (lane & 7)) * 40 + ((lane >> 3) & 1) * 8) * 2;
    const unsigned voff = ((((lane >> 3) & 1) * 8 + (lane & 7)) * 40 + ((lane >> 4) & 1) * 8) * 2;

    for (int t = warp; t < 7; t += 4) {
        const int q0 = t * 16;
        unsigned a0[4], a1[4];
        ldsm_x4(a0, sQ + q0 * 80 + qoff);
        ldsm_x4(a1, sQ + q0 * 80 + qoff + 32);

        const int rA = q0 + (lane >> 2), rB = rA + 8;
        const bool okA = rA < 98, okB = rB < 98;
        const int j0base = (lane & 3) * 2;
        unsigned pA[14], pB[14];
        float mxA = -1e30f, mxB = -1e30f;

        #pragma unroll
        for (int p = 0; p < 7; p++) {
            float s0[4] = {0.f, 0.f, 0.f, 0.f}, s1[4] = {0.f, 0.f, 0.f, 0.f};
            unsigned b[4];
            ldsm_x4(b, sK + p * 16 * 80 + koff);
            mma16816(s0, a0, b[0], b[1]);
            mma16816(s1, a0, b[2], b[3]);
            ldsm_x4(b, sK + p * 16 * 80 + koff + 32);
            mma16816(s0, a1, b[0], b[1]);
            mma16816(s1, a1, b[2], b[3]);
            #pragma unroll
            for (int h = 0; h < 2; h++) {
                const float* s = h ? s1 : s0;
                int nt = 2 * p + h;
                int j = nt * 8 + j0base;
                float va0 = s[0] * SCALE, va1 = s[1] * SCALE;
                float vb0 = s[2] * SCALE, vb1 = s[3] * SCALE;
                if (j < 98) {
                    if (okA) {
                        __nv_bfloat162 m2 = *(const __nv_bfloat162*)&Ms[rA * 98 + j];
                        va0 += __low2float(m2); va1 += __high2float(m2);
                    }
                    if (okB) {
                        __nv_bfloat162 m2 = *(const __nv_bfloat162*)&Ms[rB * 98 + j];
                        vb0 += __low2float(m2); vb1 += __high2float(m2);
                    }
                } else { va0 = va1 = vb0 = vb1 = -1e30f; }
                mxA = fmaxf(mxA, fmaxf(va0, va1));
                mxB = fmaxf(mxB, fmaxf(vb0, vb1));
                pA[nt] = pack2(va0, va1);
                pB[nt] = pack2(vb0, vb1);
            }
        }
        mxA = fmaxf(mxA, __shfl_xor_sync(0xffffffffu, mxA, 1));
        mxA = fmaxf(mxA, __shfl_xor_sync(0xffffffffu, mxA, 2));
        mxB = fmaxf(mxB, __shfl_xor_sync(0xffffffffu, mxB, 1));
        mxB = fmaxf(mxB, __shfl_xor_sync(0xffffffffu, mxB, 2));

        float sA = 0.f, sB = 0.f;
        #pragma unroll
        for (int nt = 0; nt < 14; nt++) {
            __nv_bfloat162 xa = *reinterpret_cast<__nv_bfloat162*>(&pA[nt]);
            __nv_bfloat162 xb = *reinterpret_cast<__nv_bfloat162*>(&pB[nt]);
            float e0 = __expf(__low2float(xa) - mxA), e1 = __expf(__high2float(xa) - mxA);
            float e2 = __expf(__low2float(xb) - mxB), e3 = __expf(__high2float(xb) - mxB);
            sA += e0 + e1; sB += e2 + e3;
            pA[nt] = pack2(e0, e1);
            pB[nt] = pack2(e2, e3);
        }
        sA += __shfl_xor_sync(0xffffffffu, sA, 1);
        sA += __shfl_xor_sync(0xffffffffu, sA, 2);
        sB += __shfl_xor_sync(0xffffffffu, sB, 1);
        sB += __shfl_xor_sync(0xffffffffu, sB, 2);
        const float invA = 1.f / sA, invB = 1.f / sB;

        float oacc[4][4];
        #pragma unroll
        for (int i = 0; i < 4; i++)
            #pragma unroll
            for (int j = 0; j < 4; j++) oacc[i][j] = 0.f;

        #pragma unroll
        for (int kt = 0; kt < 7; kt++) {
            unsigned pa[4];
            pa[0] = pA[2 * kt];     pa[1] = pB[2 * kt];
            pa[2] = pA[2 * kt + 1]; pa[3] = pB[2 * kt + 1];
            #pragma unroll
            for (int dp = 0; dp < 2; dp++) {
                unsigned b[4];
                ldsm_x4_t(b, sV + kt * 16 * 80 + voff + dp * 32);
                mma16816(oacc[2 * dp],     pa, b[0], b[1]);
                mma16816(oacc[2 * dp + 1], pa, b[2], b[3]);
            }
        }

        #pragma unroll
        for (int dt = 0; dt < 4; dt++) {
            int d = head * 32 + dt * 8 + (lane & 3) * 2;
            if (okA)
                *(__nv_bfloat162*)&g_attnout[(size_t)(win * 98 + rA) * 192 + d] =
                    __floats2bfloat162_rn(oacc[dt][0] * invA, oacc[dt][1] * invA);
            if (okB)
                *(__nv_bfloat162*)&g_attnout[(size_t)(win * 98 + rB) * 192 + d] =
                    __floats2bfloat162_rn(oacc[dt][2] * invB, oacc[dt][3] * invB);
        }
    }
}

// ---------------- launch ----------------------------------------------------
extern "C" void kernel_launch(void* const* d_in, const int* in_sizes, int n_in,
                              void* d_out, int out_size) {
    const float* x     = (const float*)d_in[0];
    const float* amask = (const float*)d_in[1];
    const float* n1g   = (const float*)d_in[2];
    const float* n1b   = (const float*)d_in[3];
    const float* qkvw  = (const float*)d_in[4];
    const float* qkvb  = (const float*)d_in[5];
    const float* relb  = (const float*)d_in[6];
    const float* projw = (const float*)d_in[7];
    const float* projb = (const float*)d_in[8];
    const float* fc1w  = (const float*)d_in[9];
    const float* fc1b  = (const float*)d_in[10];
    float* out = (float*)d_out;
    (void)in_sizes; (void)n_in; (void)out_size;

    const int SMEM = (128 + 64) * 192 * 2;   // 73728 B (swizzled, no padding)
    cudaFuncSetAttribute(gemm_mma<0>, cudaFuncAttributeMaxDynamicSharedMemorySize, SMEM);
    cudaFuncSetAttribute(gemm_mma<1>, cudaFuncAttributeMaxDynamicSharedMemorySize, SMEM);
    cudaFuncSetAttribute(gemm_mma<2>, cudaFuncAttributeMaxDynamicSharedMemorySize, SMEM);

    convert_w_k<<<720, 256>>>(qkvw, projw, fc1w);
    mb_combine_k<<<9604, 256>>>(amask, relb);
    ln_gather_k<<<12544, 256>>>(x, n1g, n1b);
    gemm_mma<0><<<dim3(9, 784), 256, SMEM>>>(qkvb, nullptr, nullptr);
    attn_mma<<<6144, 128>>>();
    gemm_mma<1><<<dim3(3, 784), 256, SMEM>>>(projb, nullptr, nullptr);
    gemm_mma<2><<<dim3(3, 784), 256, SMEM>>>(fc1b, x, out);
}